// round 1
// baseline (speedup 1.0000x reference)
#include <cuda_runtime.h>
#include <cfloat>

#define NN 8192
#define DD 128
#define CC 64
#define FMARGIN 0.5f
#define NSPLIT 4
#define JSPAN (NN / NSPLIT)     // 2048
#define BI 128
#define BJ 128
#define NTILES (JSPAN / BJ)     // 16
#define SROW 132                // padded floats per smem tile row

// ---------------- device scratch (no allocations allowed) ----------------
__device__ float g_xn[NN];
__device__ int   g_ps[CC * NN];        // inclusive prefix count per class
__device__ int   g_hist[CC];
__device__ float g_pv[NN * NSPLIT];
__device__ int   g_pi[NN * NSPLIT];
__device__ float g_nv[NN * NSPLIT];
__device__ int   g_ni[NN * NSPLIT];
__device__ float g_part[64 * 9];

// ---------------- K0: row squared norms ----------------
__global__ void xn_kernel(const float* __restrict__ x) {
    int row = blockIdx.x * blockDim.x + threadIdx.x;   // 64 x 128 = 8192
    const float4* xr = reinterpret_cast<const float4*>(x) + (size_t)row * 32;
    float s = 0.0f;
    #pragma unroll
    for (int q = 0; q < 32; q++) {
        float4 v = xr[q];
        s = fmaf(v.x, v.x, s);
        s = fmaf(v.y, v.y, s);
        s = fmaf(v.z, v.z, s);
        s = fmaf(v.w, v.w, s);
    }
    g_xn[row] = s;
}

// ---------------- K1: per-class inclusive prefix counts ----------------
__global__ void prefix_kernel(const int* __restrict__ tg) {
    int c = blockIdx.x;                 // one block per class
    __shared__ int wsum[8];
    __shared__ int wpre[8];
    __shared__ int stot;
    int lane = threadIdx.x & 31, wid = threadIdx.x >> 5;
    int run = 0;
    for (int base = 0; base < NN; base += 256) {
        int f = (tg[base + threadIdx.x] == c) ? 1 : 0;
        int s = f;
        #pragma unroll
        for (int o = 1; o < 32; o <<= 1) {
            int v = __shfl_up_sync(0xffffffffu, s, o);
            if (lane >= o) s += v;
        }
        if (lane == 31) wsum[wid] = s;
        __syncthreads();
        if (threadIdx.x == 0) {
            int a = 0;
            for (int w = 0; w < 8; w++) { wpre[w] = a; a += wsum[w]; }
            stot = a;
        }
        __syncthreads();
        g_ps[c * NN + base + threadIdx.x] = run + wpre[wid] + s;
        run += stot;
        __syncthreads();
    }
    if (threadIdx.x == 0) g_hist[c] = run;
}

// ---------------- K2: masked argmax/argmin over pairwise distances ----------------
// score s = xn_j - 2*dot(x_i, x_j)  (row-monotone transform of d_ij)
__global__ void __launch_bounds__(256, 1)
dist_kernel(const float* __restrict__ x, const int* __restrict__ tg) {
    extern __shared__ float smem[];
    float* As  = smem;                       // BI*SROW
    float* Bs  = As + BI * SROW;             // BJ*SROW
    float* sxn = Bs + BJ * SROW;             // 128
    int*   st  = (int*)(sxn + BJ);           // 128
    float* rpv = (float*)(st + BJ);          // 128*16
    float* rnv = rpv + BI * 16;
    int*   rpi = (int*)(rnv + BI * 16);
    int*   rni = rpi + BI * 16;

    const int tid = threadIdx.x;
    const int ty = tid >> 4;                 // 0..15 (i group)
    const int tx = tid & 15;                 // 0..15 (j group)
    const int ib = blockIdx.x * BI;
    const int jb0 = blockIdx.y * JSPAN;

    // stationary A tile (rows), coalesced copy, padded rows
    for (int l = tid; l < BI * 32; l += 256) {
        int r = l >> 5, q = l & 31;
        float4 v = reinterpret_cast<const float4*>(x)[(size_t)(ib + r) * 32 + q];
        *reinterpret_cast<float4*>(&As[r * SROW + q * 4]) = v;
    }

    int ti[8];
    #pragma unroll
    for (int ii = 0; ii < 8; ii++) ti[ii] = tg[ib + ii * 16 + ty];

    float bpv[8], bnv[8];
    int bpi[8], bni[8];
    #pragma unroll
    for (int ii = 0; ii < 8; ii++) {
        bpv[ii] = -FLT_MAX; bnv[ii] = FLT_MAX; bpi[ii] = NN; bni[ii] = NN;
    }

    for (int t = 0; t < NTILES; t++) {
        const int jb = jb0 + t * BJ;
        __syncthreads();                     // previous consumers done with Bs/sxn/st
        for (int l = tid; l < BJ * 32; l += 256) {
            int r = l >> 5, q = l & 31;
            float4 v = reinterpret_cast<const float4*>(x)[(size_t)(jb + r) * 32 + q];
            *reinterpret_cast<float4*>(&Bs[r * SROW + q * 4]) = v;
        }
        if (tid < BJ) { sxn[tid] = g_xn[jb + tid]; st[tid] = tg[jb + tid]; }
        __syncthreads();

        float acc[8][8];
        #pragma unroll
        for (int ii = 0; ii < 8; ii++) {
            #pragma unroll
            for (int jj = 0; jj < 8; jj++) acc[ii][jj] = 0.0f;
        }

        #pragma unroll 1
        for (int kq = 0; kq < 32; kq++) {
            float4 a[8];
            #pragma unroll
            for (int ii = 0; ii < 8; ii++)
                a[ii] = *reinterpret_cast<const float4*>(&As[(ii * 16 + ty) * SROW + kq * 4]);
            #pragma unroll
            for (int jj = 0; jj < 8; jj++) {
                float4 b = *reinterpret_cast<const float4*>(&Bs[(jj * 16 + tx) * SROW + kq * 4]);
                #pragma unroll
                for (int ii = 0; ii < 8; ii++) {
                    acc[ii][jj] = fmaf(a[ii].x, b.x, acc[ii][jj]);
                    acc[ii][jj] = fmaf(a[ii].y, b.y, acc[ii][jj]);
                    acc[ii][jj] = fmaf(a[ii].z, b.z, acc[ii][jj]);
                    acc[ii][jj] = fmaf(a[ii].w, b.w, acc[ii][jj]);
                }
            }
        }

        // fold this tile into the running bests (j ascending within each thread)
        #pragma unroll
        for (int jj = 0; jj < 8; jj++) {
            int jl = jj * 16 + tx;
            float xnj = sxn[jl];
            int tj = st[jl];
            int j = jb + jl;
            #pragma unroll
            for (int ii = 0; ii < 8; ii++) {
                float s = fmaf(-2.0f, acc[ii][jj], xnj);
                if (tj == ti[ii]) {
                    if (s > bpv[ii]) { bpv[ii] = s; bpi[ii] = j; }
                } else {
                    if (s < bnv[ii]) { bnv[ii] = s; bni[ii] = j; }
                }
            }
        }
    }

    // cross-thread merge per row (16 tx partials), tie -> smaller index
    __syncthreads();
    #pragma unroll
    for (int ii = 0; ii < 8; ii++) {
        int rl = ii * 16 + ty;
        rpv[rl * 16 + tx] = bpv[ii];
        rnv[rl * 16 + tx] = bnv[ii];
        rpi[rl * 16 + tx] = bpi[ii];
        rni[rl * 16 + tx] = bni[ii];
    }
    __syncthreads();
    if (tid < BI) {
        float pv = -FLT_MAX, nv = FLT_MAX;
        int pix = NN, nix = NN;
        #pragma unroll
        for (int k = 0; k < 16; k++) {
            float v = rpv[tid * 16 + k]; int id = rpi[tid * 16 + k];
            if (v > pv || (v == pv && id < pix)) { pv = v; pix = id; }
            v = rnv[tid * 16 + k]; id = rni[tid * 16 + k];
            if (v < nv || (v == nv && id < nix)) { nv = v; nix = id; }
        }
        int o = (ib + tid) * NSPLIT + blockIdx.y;
        g_pv[o] = pv; g_pi[o] = pix; g_nv[o] = nv; g_ni[o] = nix;
    }
}

// ---------------- K3: merge splits, gather triplets, per-block partial sums ----------------
__global__ void terms_kernel(const float* __restrict__ x, const int* __restrict__ tg) {
    __shared__ float red[128];
    int tid = threadIdx.x;
    int row = blockIdx.x * 128 + tid;

    float pv = -FLT_MAX, nv = FLT_MAX;
    int gp = NN, gn = NN;
    #pragma unroll
    for (int s2 = 0; s2 < NSPLIT; s2++) {
        int o = row * NSPLIT + s2;
        float v = g_pv[o]; int id = g_pi[o];
        if (v > pv || (v == pv && id < gp)) { pv = v; gp = id; }
        v = g_nv[o]; id = g_ni[o];
        if (v < nv || (v == nv && id < gn)) { nv = v; gn = id; }
    }
    int t = tg[row];
    int cs = g_hist[t];
    float vf = (cs > 1 && (NN - cs) >= 1) ? 1.0f : 0.0f;
    gp = min(max(gp, 0), NN - 1);
    gn = min(max(gn, 0), NN - 1);
    int ppos = g_ps[t * NN + gp] - 1;          // rank within same-class subset
    int pneg = gn - g_ps[t * NN + gn];          // rank within diff-class subset
    ppos = min(max(ppos, 0), NN - 1);
    pneg = min(max(pneg, 0), NN - 1);

    const float4* A = reinterpret_cast<const float4*>(x) + (size_t)row * 32;
    const float4* P = reinterpret_cast<const float4*>(x) + (size_t)ppos * 32;
    const float4* Q = reinterpret_cast<const float4*>(x) + (size_t)pneg * 32;
    float ap = 0, an = 0, npd = 0, l1a = 0, l1p = 0, l1n = 0;
    #pragma unroll
    for (int q = 0; q < 32; q++) {
        float4 a = A[q], p = P[q], n = Q[q];
        float d;
        d = a.x - p.x; ap = fmaf(d, d, ap);
        d = a.y - p.y; ap = fmaf(d, d, ap);
        d = a.z - p.z; ap = fmaf(d, d, ap);
        d = a.w - p.w; ap = fmaf(d, d, ap);
        d = a.x - n.x; an = fmaf(d, d, an);
        d = a.y - n.y; an = fmaf(d, d, an);
        d = a.z - n.z; an = fmaf(d, d, an);
        d = a.w - n.w; an = fmaf(d, d, an);
        d = p.x - n.x; npd = fmaf(d, d, npd);
        d = p.y - n.y; npd = fmaf(d, d, npd);
        d = p.z - n.z; npd = fmaf(d, d, npd);
        d = p.w - n.w; npd = fmaf(d, d, npd);
        l1a += fabsf(a.x) + fabsf(a.y) + fabsf(a.z) + fabsf(a.w);
        l1p += fabsf(p.x) + fabsf(p.y) + fabsf(p.z) + fabsf(p.w);
        l1n += fabsf(n.x) + fabsf(n.y) + fabsf(n.z) + fabsf(n.w);
    }
    float tl = fmaxf(ap - an + FMARGIN, 0.0f) * vf;

    float vals[9];
    vals[0] = tl;
    vals[1] = (tl > 0.0f) ? 1.0f : 0.0f;
    vals[2] = l1a * vf;
    vals[3] = l1p * vf;
    vals[4] = l1n * vf;
    vals[5] = ap * vf;
    vals[6] = an * vf;
    vals[7] = (ap - an - npd) * vf;
    vals[8] = vf;

    for (int k = 0; k < 9; k++) {
        red[tid] = vals[k];
        __syncthreads();
        for (int s = 64; s > 0; s >>= 1) {
            if (tid < s) red[tid] += red[tid + s];
            __syncthreads();
        }
        if (tid == 0) g_part[blockIdx.x * 9 + k] = red[0];
        __syncthreads();
    }
}

// ---------------- K4: finalize 6 scalars ----------------
__global__ void final_kernel(float* __restrict__ out, int out_size) {
    __shared__ float r[6];
    if (threadIdx.x == 0) {
        float s[9];
        for (int k = 0; k < 9; k++) s[k] = 0.0f;
        for (int b = 0; b < 64; b++)
            for (int k = 0; k < 9; k++) s[k] += g_part[b * 9 + k];
        float vcount = s[8];
        float inv = (vcount > 0.0f) ? (1.0f / vcount) : 0.0f;
        float trip = (s[1] > 0.0f) ? (s[0] / s[1]) : (s[0] * inv);
        float sparse = (s[2] + s[3] + s[4]) * inv * (1.0f / 3.0f);
        float pw = s[7] * inv;
        if (pw < 0.0f) pw = 0.0f;
        r[0] = trip; r[1] = sparse; r[2] = pw;
        r[3] = vcount; r[4] = s[5] * inv; r[5] = s[6] * inv;
    }
    __syncthreads();
    for (int i = threadIdx.x; i < out_size; i += blockDim.x)
        out[i] = (i < 6) ? r[i] : 0.0f;
}

// ---------------- launch ----------------
extern "C" void kernel_launch(void* const* d_in, const int* in_sizes, int n_in,
                              void* d_out, int out_size) {
    const float* x = (const float*)d_in[0];
    const int* tg = (const int*)d_in[1];

    const size_t smem_bytes =
        (size_t)(BI * SROW + BJ * SROW + BJ + BJ + 4 * BI * 16) * 4;  // 168,960 B
    cudaFuncSetAttribute(dist_kernel, cudaFuncAttributeMaxDynamicSharedMemorySize,
                         (int)smem_bytes);

    xn_kernel<<<64, 128>>>(x);
    prefix_kernel<<<CC, 256>>>(tg);
    dist_kernel<<<dim3(NN / BI, NSPLIT), 256, smem_bytes>>>(x, tg);
    terms_kernel<<<64, 128>>>(x, tg);
    final_kernel<<<1, 64>>>((float*)d_out, out_size);
}